// round 11
// baseline (speedup 1.0000x reference)
#include <cuda_runtime.h>
#include <cuda_fp16.h>
#include <math.h>
#include <stdint.h>

#define N_TOKENS 8192
#define D_IN     1024
#define D_OUT    1024
#define N_EXP    8

#define BM 128
#define BN 128
#define BK 64                    // floats per k-chunk
#define KCH (D_IN / BK)          // 16 chunks per expert
#define MT  (N_TOKENS / BM)      // 64
#define NT  (D_OUT / BN)         // 8
#define NPAIR 4                  // expert pairs
#define BSTEPS (KCH * NPAIR)     // 64 B-steps total
#define NTHREADS 128

#define A_TILE_BYTES 16384       // 128 x 64 fp16, fragment-packed
#define B_TILE_BYTES 16384       // 64 x 128 fp16, fragment-packed (per expert)
#define B_STAGE_BYTES (2 * B_TILE_BYTES)               // 32768 (expert pair)
#define SMEM_A   0                                     // 2 x 16384 = 32768
#define SMEM_B   32768                                 // 2 x 32768 = 65536
#define SMEM_G   98304                                 // gate 128x8 f32 (4096)
#define SMEM_BS  102400                                // bias 8x128 f32 (4096)
#define SMEM_TOTAL 106496                              // x2 CTA = 212992 < 228K

// ---------------------------------------------------------------------------
// scratch (device globals: no allocation allowed)
// ---------------------------------------------------------------------------
__device__ float  g_gate[N_TOKENS * N_EXP];
__device__ __half x_pack[(size_t)MT * KCH * 8192];           // 16 MB (ungated)
__device__ __half w_pack[(size_t)N_EXP * NT * KCH * 8192];   // 16 MB

// ---------------------------------------------------------------------------
// helpers
// ---------------------------------------------------------------------------
__device__ __forceinline__ uint32_t smem_u32(const void* p) {
    uint32_t a;
    asm("{ .reg .u64 t; cvta.to.shared.u64 t, %1; cvt.u32.u64 %0, t; }" : "=r"(a) : "l"(p));
    return a;
}
__device__ __forceinline__ void cp16(uint32_t d, const void* s) {
    asm volatile("cp.async.cg.shared.global [%0], [%1], 16;" :: "r"(d), "l"(s));
}
__device__ __forceinline__ void cp_commit() {
    asm volatile("cp.async.commit_group;" ::: "memory");
}
__device__ __forceinline__ void cp_wait0() {
    asm volatile("cp.async.wait_group 0;" ::: "memory");
}
__device__ __forceinline__ void mma_f16(float* d, const uint32_t* a,
                                        const uint32_t* b, const float* c) {
    asm volatile(
        "mma.sync.aligned.m16n8k16.row.col.f32.f16.f16.f32 "
        "{%0,%1,%2,%3}, {%4,%5,%6,%7}, {%8,%9}, {%10,%11,%12,%13};\n"
        : "=f"(d[0]), "=f"(d[1]), "=f"(d[2]), "=f"(d[3])
        : "r"(a[0]), "r"(a[1]), "r"(a[2]), "r"(a[3]),
          "r"(b[0]), "r"(b[1]),
          "f"(c[0]), "f"(c[1]), "f"(c[2]), "f"(c[3]));
}
__device__ __forceinline__ uint32_t h2u(float lo, float hi) {
    __half2 h = __halves2half2(__float2half_rn(lo), __float2half_rn(hi));
    return *reinterpret_cast<uint32_t*>(&h);
}
__device__ __forceinline__ uint32_t hmul2u(uint32_t a, uint32_t g) {
    __half2 r = __hmul2(*reinterpret_cast<__half2*>(&a), *reinterpret_cast<__half2*>(&g));
    return *reinterpret_cast<uint32_t*>(&r);
}

// ---------------------------------------------------------------------------
// Gate: g = softmax(x @ gate_W + gate_b), one warp per token
// ---------------------------------------------------------------------------
__global__ void gate_kernel(const float* __restrict__ x,
                            const float* __restrict__ gate_W,
                            const float* __restrict__ gate_b) {
    int warp = threadIdx.x >> 5, lane = threadIdx.x & 31;
    int token = blockIdx.x * 8 + warp;
    if (token >= N_TOKENS) return;
    const float* xr = x + (size_t)token * D_IN;
    float acc[N_EXP];
#pragma unroll
    for (int e = 0; e < N_EXP; e++) acc[e] = 0.f;
    for (int i = lane; i < D_IN; i += 32) {
        float xv = xr[i];
        const float4* gw = reinterpret_cast<const float4*>(gate_W + (size_t)i * N_EXP);
        float4 w0 = gw[0], w1 = gw[1];
        acc[0] += xv * w0.x; acc[1] += xv * w0.y; acc[2] += xv * w0.z; acc[3] += xv * w0.w;
        acc[4] += xv * w1.x; acc[5] += xv * w1.y; acc[6] += xv * w1.z; acc[7] += xv * w1.w;
    }
#pragma unroll
    for (int e = 0; e < N_EXP; e++)
#pragma unroll
        for (int o = 16; o > 0; o >>= 1)
            acc[e] += __shfl_xor_sync(0xffffffffu, acc[e], o);
    if (lane == 0) {
        float m = -1e30f;
#pragma unroll
        for (int e = 0; e < N_EXP; e++) { acc[e] += gate_b[e]; m = fmaxf(m, acc[e]); }
        float s = 0.f;
#pragma unroll
        for (int e = 0; e < N_EXP; e++) { acc[e] = expf(acc[e] - m); s += acc[e]; }
        float inv = 1.f / s;
#pragma unroll
        for (int e = 0; e < N_EXP; e++) g_gate[token * N_EXP + e] = acc[e] * inv;
    }
}

// ---------------------------------------------------------------------------
// pack_x: x_pack[mt][kc] = 128x64 tile of x, fp16, m16n8k16 A-fragment layout.
// ---------------------------------------------------------------------------
__global__ void pack_x_kernel(const float* __restrict__ x) {
    __shared__ float xs[128 * 68];
    const int blk = blockIdx.x;                  // mt*16 + kc
    const int kc = blk & 15, mt = blk >> 4;
    const int tid = threadIdx.x;

    const float* src = x + (size_t)(mt * BM) * D_IN + kc * BK;
    for (int idx = tid; idx < 2048; idx += 256) {
        int row = idx >> 4, c4 = idx & 15;
        float4 v = *reinterpret_cast<const float4*>(src + (size_t)row * D_IN + c4 * 4);
        *reinterpret_cast<float4*>(xs + row * 68 + c4 * 4) = v;
    }
    __syncthreads();

    __half* dst = x_pack + (size_t)blk * 8192;
#pragma unroll
    for (int q = 0; q < 4; q++) {
        int ent = tid + q * 256;                 // 0..1023
        int lane = ent & 31, m16 = (ent >> 5) & 7, ks2 = ent >> 8;
        int gid = lane >> 2, tig = lane & 3;
        int r0 = m16 * 16 + gid, r1 = r0 + 8, c0 = ks2 * 16 + 2 * tig;
        const float* x0 = xs + r0 * 68;
        const float* x1 = xs + r1 * 68;
        uint4 w;
        w.x = h2u(x0[c0],     x0[c0 + 1]);
        w.y = h2u(x1[c0],     x1[c0 + 1]);
        w.z = h2u(x0[c0 + 8], x0[c0 + 9]);
        w.w = h2u(x1[c0 + 8], x1[c0 + 9]);
        *reinterpret_cast<uint4*>(dst + ent * 8) = w;
    }
}

// ---------------------------------------------------------------------------
// pack_w: w_pack[e][nt][kc] = 64(k)x128(n) tile of W^T, fp16, B-fragment layout.
// ---------------------------------------------------------------------------
__global__ void pack_w_kernel(const float* __restrict__ W) {
    __shared__ float ws[64 * 132];
    const int blk = blockIdx.x;                  // (e*NT+nt)*16 + kc
    const int kc = blk & 15, nt = (blk >> 4) & 7, e = blk >> 7;
    const int tid = threadIdx.x;

    const float* src = W + ((size_t)e * D_IN + kc * BK) * D_OUT + nt * 128;
    for (int idx = tid; idx < 2048; idx += 256) {
        int il = idx >> 5, o4 = idx & 31;
        float4 v = *reinterpret_cast<const float4*>(src + (size_t)il * D_OUT + o4 * 4);
        *reinterpret_cast<float4*>(ws + il * 132 + o4 * 4) = v;
    }
    __syncthreads();

    __half* dst = w_pack + (size_t)blk * 8192;
#pragma unroll
    for (int q = 0; q < 4; q++) {
        int ent = tid + q * 256;                 // 0..1023
        int lane = ent & 31, jp = (ent >> 5) & 7, ks2 = ent >> 8;
        int gid = lane >> 2, tig = lane & 3;
        int kr = ks2 * 16 + 2 * tig;
        int cA = jp * 16 + gid, cB = cA + 8;
        uint4 w;
        w.x = h2u(ws[kr * 132 + cA],       ws[(kr + 1) * 132 + cA]);
        w.y = h2u(ws[(kr + 8) * 132 + cA], ws[(kr + 9) * 132 + cA]);
        w.z = h2u(ws[kr * 132 + cB],       ws[(kr + 1) * 132 + cB]);
        w.w = h2u(ws[(kr + 8) * 132 + cB], ws[(kr + 9) * 132 + cB]);
        *reinterpret_cast<uint4*>(dst + ent * 8) = w;
    }
}

// ---------------------------------------------------------------------------
// Hot GEMM: 128x128 CTA tile, 4 warps 2(m) x 2(n), warp tile 64x64, occ 2.
// Loop: kc { A staged once } x expert-pair { 2 B tiles } — A writes /8, A reads /2.
// Gate applied to A fragments in registers per expert (HMUL2).
// ---------------------------------------------------------------------------
__global__ void __launch_bounds__(NTHREADS, 2)
moe_mma_kernel(const float* __restrict__ bias, float* __restrict__ out) {
    extern __shared__ char smem[];
    const int tid = threadIdx.x, wid = tid >> 5, lane = tid & 31;
    const int gid = lane >> 2, tig = lane & 3;
    const int wm = wid >> 1, wn = wid & 1;
    const int nt = blockIdx.x & 7, mt = blockIdx.x >> 3;
    const int m0 = mt * BM, n0 = nt * BN;
    const uint32_t sb = smem_u32(smem);

    float* g_s = reinterpret_cast<float*>(smem + SMEM_G);
    float* b_s = reinterpret_cast<float*>(smem + SMEM_BS);
    for (int i = tid; i < BM * N_EXP; i += NTHREADS) g_s[i] = g_gate[m0 * N_EXP + i];
    for (int i = tid; i < N_EXP * BN; i += NTHREADS)
        b_s[i] = bias[(size_t)(i >> 7) * D_OUT + n0 + (i & 127)];

    float acc[4][8][4];
#pragma unroll
    for (int a = 0; a < 4; a++)
#pragma unroll
        for (int b = 0; b < 8; b++)
#pragma unroll
            for (int c = 0; c < 4; c++) acc[a][b][c] = 0.f;

    // stage issue helpers (8 cp16 per 16KB tile per thread)
    auto issueA = [&](int kc, int buf) {
        const char* src = (const char*)(x_pack + (size_t)(mt * KCH + kc) * 8192);
        uint32_t d = sb + SMEM_A + buf * A_TILE_BYTES + tid * 16;
#pragma unroll
        for (int r = 0; r < 8; r++) cp16(d + r * 2048, src + tid * 16 + r * 2048);
    };
    auto issueB = [&](int it, int buf) {
        const int kc = it >> 2, e0 = (it & 3) * 2;
        uint32_t d = sb + SMEM_B + buf * B_STAGE_BYTES + tid * 16;
#pragma unroll
        for (int ee = 0; ee < 2; ee++) {
            const char* src = (const char*)(
                w_pack + (size_t)(((e0 + ee) * NT + nt) * KCH + kc) * 8192);
#pragma unroll
            for (int r = 0; r < 8; r++)
                cp16(d + ee * B_TILE_BYTES + r * 2048, src + tid * 16 + r * 2048);
        }
    };

    // prologue: A0 + B0 in one group
    issueA(0, 0);
    issueB(0, 0);
    cp_commit();

    for (int it = 0; it < BSTEPS; ++it) {
        const int kc = it >> 2, e0 = (it & 3) * 2;
        cp_wait0();                  // stage `it` (and pending A) landed for this thread
        __syncthreads();             // publish; all warps done with step it-1

        // issue next B (and next A at kc boundary) — overlaps compute of `it`
        if (it + 1 < BSTEPS) {
            issueB(it + 1, (it + 1) & 1);
            if ((it & 3) == 0 && kc + 1 < KCH) issueA(kc + 1, (kc + 1) & 1);
            cp_commit();
        }

        // per-expert gate half2s for this thread's 8 A-fragment rows
        uint32_t g2e[2][4][2];
#pragma unroll
        for (int ee = 0; ee < 2; ee++)
#pragma unroll
            for (int mtt = 0; mtt < 4; mtt++) {
                int r0 = wm * 64 + mtt * 16 + gid;
                float gv0 = g_s[r0 * N_EXP + e0 + ee];
                float gv1 = g_s[(r0 + 8) * N_EXP + e0 + ee];
                g2e[ee][mtt][0] = h2u(gv0, gv0);
                g2e[ee][mtt][1] = h2u(gv1, gv1);
            }

        const char* ab = smem + SMEM_A + (kc & 1) * A_TILE_BYTES;
        const char* bb = smem + SMEM_B + (it & 1) * B_STAGE_BYTES;
#pragma unroll
        for (int ks2 = 0; ks2 < 4; ks2++) {
            uint4 af[4];
#pragma unroll
            for (int mtt = 0; mtt < 4; mtt++)
                af[mtt] = *reinterpret_cast<const uint4*>(
                    ab + (size_t)((ks2 * 8 + wm * 4 + mtt) * 32 + lane) * 16);
#pragma unroll
            for (int ee = 0; ee < 2; ee++) {
                uint4 bf[4];
#pragma unroll
                for (int jpi = 0; jpi < 4; jpi++)
                    bf[jpi] = *reinterpret_cast<const uint4*>(
                        bb + ee * B_TILE_BYTES +
                        (size_t)((ks2 * 8 + wn * 4 + jpi) * 32 + lane) * 16);
                uint4 afg[4];
#pragma unroll
                for (int mtt = 0; mtt < 4; mtt++) {
                    afg[mtt].x = hmul2u(af[mtt].x, g2e[ee][mtt][0]);
                    afg[mtt].y = hmul2u(af[mtt].y, g2e[ee][mtt][1]);
                    afg[mtt].z = hmul2u(af[mtt].z, g2e[ee][mtt][0]);
                    afg[mtt].w = hmul2u(af[mtt].w, g2e[ee][mtt][1]);
                }
#pragma unroll
                for (int mtt = 0; mtt < 4; mtt++)
#pragma unroll
                    for (int ntt = 0; ntt < 8; ntt++) {
                        const uint32_t* a = reinterpret_cast<const uint32_t*>(&afg[mtt]);
                        const uint32_t* bp =
                            reinterpret_cast<const uint32_t*>(&bf[ntt >> 1]) + (ntt & 1) * 2;
                        mma_f16(acc[mtt][ntt], a, bp, acc[mtt][ntt]);
                    }
            }
        }
    }

    // ---- epilogue: gated bias + store ----
#pragma unroll
    for (int mtt = 0; mtt < 4; mtt++) {
        const int rb = wm * 64 + mtt * 16 + gid;
#pragma unroll
        for (int half = 0; half < 2; half++) {
            const int r = rb + half * 8;
            const float* gr = g_s + r * N_EXP;
            float* orow = out + (size_t)(m0 + r) * D_OUT + n0;
#pragma unroll
            for (int ntt = 0; ntt < 8; ntt++) {
                const int c = wn * 64 + ntt * 8 + 2 * tig;
                float b0 = 0.f, b1 = 0.f;
#pragma unroll
                for (int e = 0; e < N_EXP; e++) {
                    float gv = gr[e];
                    b0 += gv * b_s[e * BN + c];
                    b1 += gv * b_s[e * BN + c + 1];
                }
                float2 v;
                v.x = acc[mtt][ntt][half * 2 + 0] + b0;
                v.y = acc[mtt][ntt][half * 2 + 1] + b1;
                *reinterpret_cast<float2*>(orow + c) = v;
            }
        }
    }
}

// ---------------------------------------------------------------------------
extern "C" void kernel_launch(void* const* d_in, const int* in_sizes, int n_in,
                              void* d_out, int out_size) {
    const float* x      = (const float*)d_in[0];
    const float* W      = (const float*)d_in[1];
    const float* b      = (const float*)d_in[2];
    const float* gate_W = (const float*)d_in[3];
    const float* gate_b = (const float*)d_in[4];
    float* out = (float*)d_out;

    gate_kernel<<<N_TOKENS / 8, 256>>>(x, gate_W, gate_b);
    pack_x_kernel<<<MT * KCH, 256>>>(x);           // 1024 blocks
    pack_w_kernel<<<N_EXP * NT * KCH, 256>>>(W);   // 1024 blocks

    cudaFuncSetAttribute(moe_mma_kernel,
                         cudaFuncAttributeMaxDynamicSharedMemorySize, SMEM_TOTAL);
    moe_mma_kernel<<<MT * NT, NTHREADS, SMEM_TOTAL>>>(b, out);   // 512 CTAs
}

// round 12
// speedup vs baseline: 1.4598x; 1.4598x over previous
#include <cuda_runtime.h>
#include <cuda_fp16.h>
#include <math.h>
#include <stdint.h>

#define N_TOKENS 8192
#define D_IN     1024
#define D_OUT    1024
#define N_EXP    8

#define BM 128
#define BN 128
#define BK 64
#define KCH (D_IN / BK)          // 16
#define MT  (N_TOKENS / BM)      // 64
#define NT  (D_OUT / BN)         // 8
#define NTHREADS 128
#define TSTEPS (KCH * 4 * N_EXP) // 512 (kc, ks2, e) flat steps

#define A_TILE_BYTES 16384       // 128 x 64 fp16, fragment-packed
#define SMEM_A   0               // 3 x 16384 = 49152
#define SMEM_GS  49152           // gate float 128x8        (4096)
#define SMEM_GH  53248           // gate half2-broadcast    (4096)
#define SMEM_BS  57344           // bias 8x128 f32          (4096)
#define SMEM_TOTAL 61440

// ---------------------------------------------------------------------------
__device__ float  g_gate[N_TOKENS * N_EXP];
__device__ __half x_pack[(size_t)MT * KCH * 8192];           // 16 MB
__device__ __half w_pack[(size_t)N_EXP * NT * KCH * 8192];   // 16 MB

// ---------------------------------------------------------------------------
__device__ __forceinline__ uint32_t smem_u32(const void* p) {
    uint32_t a;
    asm("{ .reg .u64 t; cvta.to.shared.u64 t, %1; cvt.u32.u64 %0, t; }" : "=r"(a) : "l"(p));
    return a;
}
__device__ __forceinline__ void cp16(uint32_t d, const void* s) {
    asm volatile("cp.async.cg.shared.global [%0], [%1], 16;" :: "r"(d), "l"(s));
}
__device__ __forceinline__ void cp_commit() {
    asm volatile("cp.async.commit_group;" ::: "memory");
}
__device__ __forceinline__ void cp_wait1() {
    asm volatile("cp.async.wait_group 1;" ::: "memory");
}
__device__ __forceinline__ void mma_f16(float* d, const uint32_t* a,
                                        const uint32_t* b, const float* c) {
    asm volatile(
        "mma.sync.aligned.m16n8k16.row.col.f32.f16.f16.f32 "
        "{%0,%1,%2,%3}, {%4,%5,%6,%7}, {%8,%9}, {%10,%11,%12,%13};\n"
        : "=f"(d[0]), "=f"(d[1]), "=f"(d[2]), "=f"(d[3])
        : "r"(a[0]), "r"(a[1]), "r"(a[2]), "r"(a[3]),
          "r"(b[0]), "r"(b[1]),
          "f"(c[0]), "f"(c[1]), "f"(c[2]), "f"(c[3]));
}
__device__ __forceinline__ uint32_t h2u(float lo, float hi) {
    __half2 h = __halves2half2(__float2half_rn(lo), __float2half_rn(hi));
    return *reinterpret_cast<uint32_t*>(&h);
}
__device__ __forceinline__ uint32_t hmul2u(uint32_t a, uint32_t g) {
    __half2 r = __hmul2(*reinterpret_cast<__half2*>(&a), *reinterpret_cast<__half2*>(&g));
    return *reinterpret_cast<uint32_t*>(&r);
}

// ---------------------------------------------------------------------------
// Gate: g = softmax(x @ gate_W + gate_b), one warp per token
// ---------------------------------------------------------------------------
__global__ void gate_kernel(const float* __restrict__ x,
                            const float* __restrict__ gate_W,
                            const float* __restrict__ gate_b) {
    int warp = threadIdx.x >> 5, lane = threadIdx.x & 31;
    int token = blockIdx.x * 8 + warp;
    if (token >= N_TOKENS) return;
    const float* xr = x + (size_t)token * D_IN;
    float acc[N_EXP];
#pragma unroll
    for (int e = 0; e < N_EXP; e++) acc[e] = 0.f;
    for (int i = lane; i < D_IN; i += 32) {
        float xv = xr[i];
        const float4* gw = reinterpret_cast<const float4*>(gate_W + (size_t)i * N_EXP);
        float4 w0 = gw[0], w1 = gw[1];
        acc[0] += xv * w0.x; acc[1] += xv * w0.y; acc[2] += xv * w0.z; acc[3] += xv * w0.w;
        acc[4] += xv * w1.x; acc[5] += xv * w1.y; acc[6] += xv * w1.z; acc[7] += xv * w1.w;
    }
#pragma unroll
    for (int e = 0; e < N_EXP; e++)
#pragma unroll
        for (int o = 16; o > 0; o >>= 1)
            acc[e] += __shfl_xor_sync(0xffffffffu, acc[e], o);
    if (lane == 0) {
        float m = -1e30f;
#pragma unroll
        for (int e = 0; e < N_EXP; e++) { acc[e] += gate_b[e]; m = fmaxf(m, acc[e]); }
        float s = 0.f;
#pragma unroll
        for (int e = 0; e < N_EXP; e++) { acc[e] = expf(acc[e] - m); s += acc[e]; }
        float inv = 1.f / s;
#pragma unroll
        for (int e = 0; e < N_EXP; e++) g_gate[token * N_EXP + e] = acc[e] * inv;
    }
}

// ---------------------------------------------------------------------------
// pack_x: x_pack[mt][kc] = 128x64 tile of x, fp16, m16n8k16 A-fragment layout.
// ---------------------------------------------------------------------------
__global__ void pack_x_kernel(const float* __restrict__ x) {
    __shared__ float xs[128 * 68];
    const int blk = blockIdx.x;                  // mt*16 + kc
    const int kc = blk & 15, mt = blk >> 4;
    const int tid = threadIdx.x;

    const float* src = x + (size_t)(mt * BM) * D_IN + kc * BK;
    for (int idx = tid; idx < 2048; idx += 256) {
        int row = idx >> 4, c4 = idx & 15;
        float4 v = *reinterpret_cast<const float4*>(src + (size_t)row * D_IN + c4 * 4);
        *reinterpret_cast<float4*>(xs + row * 68 + c4 * 4) = v;
    }
    __syncthreads();

    __half* dst = x_pack + (size_t)blk * 8192;
#pragma unroll
    for (int q = 0; q < 4; q++) {
        int ent = tid + q * 256;
        int lane = ent & 31, m16 = (ent >> 5) & 7, ks2 = ent >> 8;
        int gid = lane >> 2, tig = lane & 3;
        int r0 = m16 * 16 + gid, r1 = r0 + 8, c0 = ks2 * 16 + 2 * tig;
        const float* x0 = xs + r0 * 68;
        const float* x1 = xs + r1 * 68;
        uint4 w;
        w.x = h2u(x0[c0],     x0[c0 + 1]);
        w.y = h2u(x1[c0],     x1[c0 + 1]);
        w.z = h2u(x0[c0 + 8], x0[c0 + 9]);
        w.w = h2u(x1[c0 + 8], x1[c0 + 9]);
        *reinterpret_cast<uint4*>(dst + ent * 8) = w;
    }
}

// ---------------------------------------------------------------------------
// pack_w: w_pack[e][nt][kc] = 64(k)x128(n) tile of W^T, fp16, B-fragment layout.
// ---------------------------------------------------------------------------
__global__ void pack_w_kernel(const float* __restrict__ W) {
    __shared__ float ws[64 * 132];
    const int blk = blockIdx.x;                  // (e*NT+nt)*16 + kc
    const int kc = blk & 15, nt = (blk >> 4) & 7, e = blk >> 7;
    const int tid = threadIdx.x;

    const float* src = W + ((size_t)e * D_IN + kc * BK) * D_OUT + nt * 128;
    for (int idx = tid; idx < 2048; idx += 256) {
        int il = idx >> 5, o4 = idx & 31;
        float4 v = *reinterpret_cast<const float4*>(src + (size_t)il * D_OUT + o4 * 4);
        *reinterpret_cast<float4*>(ws + il * 132 + o4 * 4) = v;
    }
    __syncthreads();

    __half* dst = w_pack + (size_t)blk * 8192;
#pragma unroll
    for (int q = 0; q < 4; q++) {
        int ent = tid + q * 256;
        int lane = ent & 31, jp = (ent >> 5) & 7, ks2 = ent >> 8;
        int gid = lane >> 2, tig = lane & 3;
        int kr = ks2 * 16 + 2 * tig;
        int cA = jp * 16 + gid, cB = cA + 8;
        uint4 w;
        w.x = h2u(ws[kr * 132 + cA],       ws[(kr + 1) * 132 + cA]);
        w.y = h2u(ws[(kr + 8) * 132 + cA], ws[(kr + 9) * 132 + cA]);
        w.z = h2u(ws[kr * 132 + cB],       ws[(kr + 1) * 132 + cB]);
        w.w = h2u(ws[(kr + 8) * 132 + cB], ws[(kr + 9) * 132 + cB]);
        *reinterpret_cast<uint4*>(dst + ent * 8) = w;
    }
}

// ---------------------------------------------------------------------------
// Hot GEMM: 128x128 CTA tile, 4 warps 2(m) x 2(n), warp tile 64x64, occ 2.
// A: 3-stage cp.async smem, staged once per kc, af held across 8 experts.
// B: direct LDG.128 from fragment-packed global (L2/L1), rolling prefetch.
// Barriers only at kc boundaries (16 total). Gate via HMUL2 on A fragments.
// ---------------------------------------------------------------------------
__global__ void __launch_bounds__(NTHREADS, 2)
moe_mma_kernel(const float* __restrict__ bias, float* __restrict__ out) {
    extern __shared__ char smem[];
    const int tid = threadIdx.x, wid = tid >> 5, lane = tid & 31;
    const int gid = lane >> 2, tig = lane & 3;
    const int wm = wid >> 1, wn = wid & 1;
    // co-resident CTAs share nt (B operand) -> B LDGs hit L1/L2
    const int nt = blockIdx.x >> 6, mt = blockIdx.x & 63;
    const int m0 = mt * BM, n0 = nt * BN;
    const uint32_t sb = smem_u32(smem);

    float*    g_s  = reinterpret_cast<float*>(smem + SMEM_GS);
    uint32_t* gh_s = reinterpret_cast<uint32_t*>(smem + SMEM_GH);
    float*    b_s  = reinterpret_cast<float*>(smem + SMEM_BS);
    for (int i = tid; i < BM * N_EXP; i += NTHREADS) {
        float g = g_gate[m0 * N_EXP + i];
        g_s[i] = g;
        gh_s[i] = h2u(g, g);
    }
    for (int i = tid; i < N_EXP * BN; i += NTHREADS)
        b_s[i] = bias[(size_t)(i >> 7) * D_OUT + n0 + (i & 127)];

    float acc[4][8][4];
#pragma unroll
    for (int a = 0; a < 4; a++)
#pragma unroll
        for (int b = 0; b < 8; b++)
#pragma unroll
            for (int c = 0; c < 4; c++) acc[a][b][c] = 0.f;

    auto issueA = [&](int kc, int buf) {
        const char* src = (const char*)(x_pack + (size_t)(mt * KCH + kc) * 8192);
        uint32_t d = sb + SMEM_A + buf * A_TILE_BYTES + tid * 16;
#pragma unroll
        for (int r = 0; r < 8; r++) cp16(d + r * 2048, src + tid * 16 + r * 2048);
        cp_commit();
    };

    // flat step t = ((kc*4 + ks2) << 3) + e ; B fragment base for step t
    auto bload = [&](int t, uint4* dst) {
        int kcx = t >> 5, ks2x = (t >> 3) & 3, ex = t & 7;
        const uint4* p = reinterpret_cast<const uint4*>(
            (const char*)w_pack +
            ((size_t)(ex * (NT * KCH) + nt * KCH + kcx)) * (8192 * 2) +
            (size_t)(((ks2x * 8 + wn * 4) * 32) + lane) * 16);
        dst[0] = __ldg(p);
        dst[1] = __ldg(p + 32);
        dst[2] = __ldg(p + 64);
        dst[3] = __ldg(p + 96);
    };

    issueA(0, 0);
    issueA(1, 1);

    uint4 bf_n[4];
    bload(0, bf_n);

    __syncthreads();   // publish g_s/gh_s/b_s (and order before first A wait)

    for (int kc = 0; kc < KCH; ++kc) {
        cp_wait1();              // A(kc) landed (A(kc+1) may be pending)
        __syncthreads();         // all warps past kc-1's compute; A(kc) visible
        if (kc + 2 < KCH) issueA(kc + 2, (kc + 2) % 3);

        const char* ab = smem + SMEM_A + (kc % 3) * A_TILE_BYTES;
#pragma unroll
        for (int ks2 = 0; ks2 < 4; ++ks2) {
            uint4 af[4];
#pragma unroll
            for (int mtt = 0; mtt < 4; mtt++)
                af[mtt] = *reinterpret_cast<const uint4*>(
                    ab + (size_t)((ks2 * 8 + wm * 4 + mtt) * 32 + lane) * 16);

#pragma unroll 2
            for (int e = 0; e < N_EXP; ++e) {
                const int t = ((kc * 4 + ks2) << 3) + e;
                uint4 bf[4];
#pragma unroll
                for (int j = 0; j < 4; j++) bf[j] = bf_n[j];
                if (t + 1 < TSTEPS) bload(t + 1, bf_n);   // prefetch next step

                uint32_t ga, gb;
#pragma unroll
                for (int mtt = 0; mtt < 4; mtt++) {
                    int r0 = wm * 64 + mtt * 16 + gid;
                    ga = gh_s[r0 * N_EXP + e];
                    gb = gh_s[(r0 + 8) * N_EXP + e];
                    uint4 afg;
                    afg.x = hmul2u(af[mtt].x, ga);
                    afg.y = hmul2u(af[mtt].y, gb);
                    afg.z = hmul2u(af[mtt].z, ga);
                    afg.w = hmul2u(af[mtt].w, gb);
                    const uint32_t* a = reinterpret_cast<const uint32_t*>(&afg);
#pragma unroll
                    for (int ntt = 0; ntt < 8; ntt++) {
                        const uint32_t* bp =
                            reinterpret_cast<const uint32_t*>(&bf[ntt >> 1]) + (ntt & 1) * 2;
                        mma_f16(acc[mtt][ntt], a, bp, acc[mtt][ntt]);
                    }
                }
            }
        }
    }

    // ---- epilogue: gated bias + store ----
#pragma unroll
    for (int mtt = 0; mtt < 4; mtt++) {
        const int rb = wm * 64 + mtt * 16 + gid;
#pragma unroll
        for (int half = 0; half < 2; half++) {
            const int r = rb + half * 8;
            const float* gr = g_s + r * N_EXP;
            float* orow = out + (size_t)(m0 + r) * D_OUT + n0;
#pragma unroll
            for (int ntt = 0; ntt < 8; ntt++) {
                const int c = wn * 64 + ntt * 8 + 2 * tig;
                float b0 = 0.f, b1 = 0.f;
#pragma unroll
                for (int e = 0; e < N_EXP; e++) {
                    float gv = gr[e];
                    b0 += gv * b_s[e * BN + c];
                    b1 += gv * b_s[e * BN + c + 1];
                }
                float2 v;
                v.x = acc[mtt][ntt][half * 2 + 0] + b0;
                v.y = acc[mtt][ntt][half * 2 + 1] + b1;
                *reinterpret_cast<float2*>(orow + c) = v;
            }
        }
    }
}

// ---------------------------------------------------------------------------
extern "C" void kernel_launch(void* const* d_in, const int* in_sizes, int n_in,
                              void* d_out, int out_size) {
    const float* x      = (const float*)d_in[0];
    const float* W      = (const float*)d_in[1];
    const float* b      = (const float*)d_in[2];
    const float* gate_W = (const float*)d_in[3];
    const float* gate_b = (const float*)d_in[4];
    float* out = (float*)d_out;

    gate_kernel<<<N_TOKENS / 8, 256>>>(x, gate_W, gate_b);
    pack_x_kernel<<<MT * KCH, 256>>>(x);           // 1024 blocks
    pack_w_kernel<<<N_EXP * NT * KCH, 256>>>(W);   // 1024 blocks

    cudaFuncSetAttribute(moe_mma_kernel,
                         cudaFuncAttributeMaxDynamicSharedMemorySize, SMEM_TOTAL);
    moe_mma_kernel<<<MT * NT, NTHREADS, SMEM_TOTAL>>>(b, out);   // 512 CTAs
}

// round 13
// speedup vs baseline: 1.4625x; 1.0018x over previous
#include <cuda_runtime.h>
#include <cuda_fp16.h>
#include <math.h>
#include <stdint.h>

#define N_TOKENS 8192
#define D_IN     1024
#define D_OUT    1024
#define N_EXP    8

#define BM 128
#define BN 128
#define BK 64
#define KCH (D_IN / BK)          // 16
#define MT  (N_TOKENS / BM)      // 64
#define NT  (D_OUT / BN)         // 8
#define NTHREADS 128
#define TSTEPS (KCH * 4 * N_EXP) // 512 (kc, ks2, e) flat steps

#define A_TILE_BYTES 16384       // 128 x 64 fp16, fragment-packed
#define SMEM_A   0               // 3 x 16384 = 49152
#define SMEM_GS  49152           // gate float 128x8        (4096)
#define SMEM_GH  53248           // gate half2-broadcast    (4096)
#define SMEM_BS  57344           // bias 8x128 f32          (4096)
#define SMEM_TOTAL 61440

// ---------------------------------------------------------------------------
__device__ float  g_gate[N_TOKENS * N_EXP];
__device__ __half x_pack[(size_t)MT * KCH * 8192];           // 16 MB
__device__ __half w_pack[(size_t)N_EXP * NT * KCH * 8192];   // 16 MB

// ---------------------------------------------------------------------------
__device__ __forceinline__ uint32_t smem_u32(const void* p) {
    uint32_t a;
    asm("{ .reg .u64 t; cvta.to.shared.u64 t, %1; cvt.u32.u64 %0, t; }" : "=r"(a) : "l"(p));
    return a;
}
__device__ __forceinline__ void cp16(uint32_t d, const void* s) {
    asm volatile("cp.async.cg.shared.global [%0], [%1], 16;" :: "r"(d), "l"(s));
}
__device__ __forceinline__ void cp_commit() {
    asm volatile("cp.async.commit_group;" ::: "memory");
}
__device__ __forceinline__ void cp_wait1() {
    asm volatile("cp.async.wait_group 1;" ::: "memory");
}
__device__ __forceinline__ void mma_f16(float* d, const uint32_t* a,
                                        const uint32_t* b, const float* c) {
    asm volatile(
        "mma.sync.aligned.m16n8k16.row.col.f32.f16.f16.f32 "
        "{%0,%1,%2,%3}, {%4,%5,%6,%7}, {%8,%9}, {%10,%11,%12,%13};\n"
        : "=f"(d[0]), "=f"(d[1]), "=f"(d[2]), "=f"(d[3])
        : "r"(a[0]), "r"(a[1]), "r"(a[2]), "r"(a[3]),
          "r"(b[0]), "r"(b[1]),
          "f"(c[0]), "f"(c[1]), "f"(c[2]), "f"(c[3]));
}
__device__ __forceinline__ uint32_t h2u(float lo, float hi) {
    __half2 h = __halves2half2(__float2half_rn(lo), __float2half_rn(hi));
    return *reinterpret_cast<uint32_t*>(&h);
}
__device__ __forceinline__ uint32_t hmul2u(uint32_t a, uint32_t g) {
    __half2 r = __hmul2(*reinterpret_cast<__half2*>(&a), *reinterpret_cast<__half2*>(&g));
    return *reinterpret_cast<uint32_t*>(&r);
}

// ---------------------------------------------------------------------------
// Gate: g = softmax(x @ gate_W + gate_b), one warp per token
// ---------------------------------------------------------------------------
__global__ void gate_kernel(const float* __restrict__ x,
                            const float* __restrict__ gate_W,
                            const float* __restrict__ gate_b) {
    int warp = threadIdx.x >> 5, lane = threadIdx.x & 31;
    int token = blockIdx.x * 8 + warp;
    if (token >= N_TOKENS) return;
    const float* xr = x + (size_t)token * D_IN;
    float acc[N_EXP];
#pragma unroll
    for (int e = 0; e < N_EXP; e++) acc[e] = 0.f;
    for (int i = lane; i < D_IN; i += 32) {
        float xv = xr[i];
        const float4* gw = reinterpret_cast<const float4*>(gate_W + (size_t)i * N_EXP);
        float4 w0 = gw[0], w1 = gw[1];
        acc[0] += xv * w0.x; acc[1] += xv * w0.y; acc[2] += xv * w0.z; acc[3] += xv * w0.w;
        acc[4] += xv * w1.x; acc[5] += xv * w1.y; acc[6] += xv * w1.z; acc[7] += xv * w1.w;
    }
#pragma unroll
    for (int e = 0; e < N_EXP; e++)
#pragma unroll
        for (int o = 16; o > 0; o >>= 1)
            acc[e] += __shfl_xor_sync(0xffffffffu, acc[e], o);
    if (lane == 0) {
        float m = -1e30f;
#pragma unroll
        for (int e = 0; e < N_EXP; e++) { acc[e] += gate_b[e]; m = fmaxf(m, acc[e]); }
        float s = 0.f;
#pragma unroll
        for (int e = 0; e < N_EXP; e++) { acc[e] = expf(acc[e] - m); s += acc[e]; }
        float inv = 1.f / s;
#pragma unroll
        for (int e = 0; e < N_EXP; e++) g_gate[token * N_EXP + e] = acc[e] * inv;
    }
}

// ---------------------------------------------------------------------------
// pack_x: x_pack[mt][kc] = 128x64 tile of x, fp16, m16n8k16 A-fragment layout.
// ---------------------------------------------------------------------------
__global__ void pack_x_kernel(const float* __restrict__ x) {
    __shared__ float xs[128 * 68];
    const int blk = blockIdx.x;                  // mt*16 + kc
    const int kc = blk & 15, mt = blk >> 4;
    const int tid = threadIdx.x;

    const float* src = x + (size_t)(mt * BM) * D_IN + kc * BK;
    for (int idx = tid; idx < 2048; idx += 256) {
        int row = idx >> 4, c4 = idx & 15;
        float4 v = *reinterpret_cast<const float4*>(src + (size_t)row * D_IN + c4 * 4);
        *reinterpret_cast<float4*>(xs + row * 68 + c4 * 4) = v;
    }
    __syncthreads();

    __half* dst = x_pack + (size_t)blk * 8192;
#pragma unroll
    for (int q = 0; q < 4; q++) {
        int ent = tid + q * 256;
        int lane = ent & 31, m16 = (ent >> 5) & 7, ks2 = ent >> 8;
        int gid = lane >> 2, tig = lane & 3;
        int r0 = m16 * 16 + gid, r1 = r0 + 8, c0 = ks2 * 16 + 2 * tig;
        const float* x0 = xs + r0 * 68;
        const float* x1 = xs + r1 * 68;
        uint4 w;
        w.x = h2u(x0[c0],     x0[c0 + 1]);
        w.y = h2u(x1[c0],     x1[c0 + 1]);
        w.z = h2u(x0[c0 + 8], x0[c0 + 9]);
        w.w = h2u(x1[c0 + 8], x1[c0 + 9]);
        *reinterpret_cast<uint4*>(dst + ent * 8) = w;
    }
}

// ---------------------------------------------------------------------------
// pack_w: w_pack[e][nt][kc] = 64(k)x128(n) tile of W^T, fp16, B-fragment layout.
// ---------------------------------------------------------------------------
__global__ void pack_w_kernel(const float* __restrict__ W) {
    __shared__ float ws[64 * 132];
    const int blk = blockIdx.x;                  // (e*NT+nt)*16 + kc
    const int kc = blk & 15, nt = (blk >> 4) & 7, e = blk >> 7;
    const int tid = threadIdx.x;

    const float* src = W + ((size_t)e * D_IN + kc * BK) * D_OUT + nt * 128;
    for (int idx = tid; idx < 2048; idx += 256) {
        int il = idx >> 5, o4 = idx & 31;
        float4 v = *reinterpret_cast<const float4*>(src + (size_t)il * D_OUT + o4 * 4);
        *reinterpret_cast<float4*>(ws + il * 132 + o4 * 4) = v;
    }
    __syncthreads();

    __half* dst = w_pack + (size_t)blk * 8192;
#pragma unroll
    for (int q = 0; q < 4; q++) {
        int ent = tid + q * 256;
        int lane = ent & 31, jp = (ent >> 5) & 7, ks2 = ent >> 8;
        int gid = lane >> 2, tig = lane & 3;
        int kr = ks2 * 16 + 2 * tig;
        int cA = jp * 16 + gid, cB = cA + 8;
        uint4 w;
        w.x = h2u(ws[kr * 132 + cA],       ws[(kr + 1) * 132 + cA]);
        w.y = h2u(ws[(kr + 8) * 132 + cA], ws[(kr + 9) * 132 + cA]);
        w.z = h2u(ws[kr * 132 + cB],       ws[(kr + 1) * 132 + cB]);
        w.w = h2u(ws[(kr + 8) * 132 + cB], ws[(kr + 9) * 132 + cB]);
        *reinterpret_cast<uint4*>(dst + ent * 8) = w;
    }
}

// ---------------------------------------------------------------------------
// Hot GEMM: 128x128 CTA tile, 4 warps 2(m) x 2(n), warp tile 64x64, occ 2.
// A: 3-stage cp.async smem, staged once per kc, af held across 8 experts.
// B: direct LDG.128 from fragment-packed global (L2/L1), rolling prefetch.
// Barriers only at kc boundaries (16 total). Gate via HMUL2 on A fragments.
// ---------------------------------------------------------------------------
__global__ void __launch_bounds__(NTHREADS, 2)
moe_mma_kernel(const float* __restrict__ bias, float* __restrict__ out) {
    extern __shared__ char smem[];
    const int tid = threadIdx.x, wid = tid >> 5, lane = tid & 31;
    const int gid = lane >> 2, tig = lane & 3;
    const int wm = wid >> 1, wn = wid & 1;
    // co-resident CTAs share nt (B operand) -> B LDGs hit L1/L2
    const int nt = blockIdx.x >> 6, mt = blockIdx.x & 63;
    const int m0 = mt * BM, n0 = nt * BN;
    const uint32_t sb = smem_u32(smem);

    float*    g_s  = reinterpret_cast<float*>(smem + SMEM_GS);
    uint32_t* gh_s = reinterpret_cast<uint32_t*>(smem + SMEM_GH);
    float*    b_s  = reinterpret_cast<float*>(smem + SMEM_BS);
    for (int i = tid; i < BM * N_EXP; i += NTHREADS) {
        float g = g_gate[m0 * N_EXP + i];
        g_s[i] = g;
        gh_s[i] = h2u(g, g);
    }
    for (int i = tid; i < N_EXP * BN; i += NTHREADS)
        b_s[i] = bias[(size_t)(i >> 7) * D_OUT + n0 + (i & 127)];

    float acc[4][8][4];
#pragma unroll
    for (int a = 0; a < 4; a++)
#pragma unroll
        for (int b = 0; b < 8; b++)
#pragma unroll
            for (int c = 0; c < 4; c++) acc[a][b][c] = 0.f;

    auto issueA = [&](int kc, int buf) {
        const char* src = (const char*)(x_pack + (size_t)(mt * KCH + kc) * 8192);
        uint32_t d = sb + SMEM_A + buf * A_TILE_BYTES + tid * 16;
#pragma unroll
        for (int r = 0; r < 8; r++) cp16(d + r * 2048, src + tid * 16 + r * 2048);
        cp_commit();
    };

    // flat step t = ((kc*4 + ks2) << 3) + e ; B fragment base for step t
    auto bload = [&](int t, uint4* dst) {
        int kcx = t >> 5, ks2x = (t >> 3) & 3, ex = t & 7;
        const uint4* p = reinterpret_cast<const uint4*>(
            (const char*)w_pack +
            ((size_t)(ex * (NT * KCH) + nt * KCH + kcx)) * (8192 * 2) +
            (size_t)(((ks2x * 8 + wn * 4) * 32) + lane) * 16);
        dst[0] = __ldg(p);
        dst[1] = __ldg(p + 32);
        dst[2] = __ldg(p + 64);
        dst[3] = __ldg(p + 96);
    };

    issueA(0, 0);
    issueA(1, 1);

    uint4 bf_n[4];
    bload(0, bf_n);

    __syncthreads();   // publish g_s/gh_s/b_s (and order before first A wait)

    for (int kc = 0; kc < KCH; ++kc) {
        cp_wait1();              // A(kc) landed (A(kc+1) may be pending)
        __syncthreads();         // all warps past kc-1's compute; A(kc) visible
        if (kc + 2 < KCH) issueA(kc + 2, (kc + 2) % 3);

        const char* ab = smem + SMEM_A + (kc % 3) * A_TILE_BYTES;
#pragma unroll
        for (int ks2 = 0; ks2 < 4; ++ks2) {
            uint4 af[4];
#pragma unroll
            for (int mtt = 0; mtt < 4; mtt++)
                af[mtt] = *reinterpret_cast<const uint4*>(
                    ab + (size_t)((ks2 * 8 + wm * 4 + mtt) * 32 + lane) * 16);

#pragma unroll 2
            for (int e = 0; e < N_EXP; ++e) {
                const int t = ((kc * 4 + ks2) << 3) + e;
                uint4 bf[4];
#pragma unroll
                for (int j = 0; j < 4; j++) bf[j] = bf_n[j];
                if (t + 1 < TSTEPS) bload(t + 1, bf_n);   // prefetch next step

                uint32_t ga, gb;
#pragma unroll
                for (int mtt = 0; mtt < 4; mtt++) {
                    int r0 = wm * 64 + mtt * 16 + gid;
                    ga = gh_s[r0 * N_EXP + e];
                    gb = gh_s[(r0 + 8) * N_EXP + e];
                    uint4 afg;
                    afg.x = hmul2u(af[mtt].x, ga);
                    afg.y = hmul2u(af[mtt].y, gb);
                    afg.z = hmul2u(af[mtt].z, ga);
                    afg.w = hmul2u(af[mtt].w, gb);
                    const uint32_t* a = reinterpret_cast<const uint32_t*>(&afg);
#pragma unroll
                    for (int ntt = 0; ntt < 8; ntt++) {
                        const uint32_t* bp =
                            reinterpret_cast<const uint32_t*>(&bf[ntt >> 1]) + (ntt & 1) * 2;
                        mma_f16(acc[mtt][ntt], a, bp, acc[mtt][ntt]);
                    }
                }
            }
        }
    }

    // ---- epilogue: gated bias + store ----
#pragma unroll
    for (int mtt = 0; mtt < 4; mtt++) {
        const int rb = wm * 64 + mtt * 16 + gid;
#pragma unroll
        for (int half = 0; half < 2; half++) {
            const int r = rb + half * 8;
            const float* gr = g_s + r * N_EXP;
            float* orow = out + (size_t)(m0 + r) * D_OUT + n0;
#pragma unroll
            for (int ntt = 0; ntt < 8; ntt++) {
                const int c = wn * 64 + ntt * 8 + 2 * tig;
                float b0 = 0.f, b1 = 0.f;
#pragma unroll
                for (int e = 0; e < N_EXP; e++) {
                    float gv = gr[e];
                    b0 += gv * b_s[e * BN + c];
                    b1 += gv * b_s[e * BN + c + 1];
                }
                float2 v;
                v.x = acc[mtt][ntt][half * 2 + 0] + b0;
                v.y = acc[mtt][ntt][half * 2 + 1] + b1;
                *reinterpret_cast<float2*>(orow + c) = v;
            }
        }
    }
}

// ---------------------------------------------------------------------------
extern "C" void kernel_launch(void* const* d_in, const int* in_sizes, int n_in,
                              void* d_out, int out_size) {
    const float* x      = (const float*)d_in[0];
    const float* W      = (const float*)d_in[1];
    const float* b      = (const float*)d_in[2];
    const float* gate_W = (const float*)d_in[3];
    const float* gate_b = (const float*)d_in[4];
    float* out = (float*)d_out;

    gate_kernel<<<N_TOKENS / 8, 256>>>(x, gate_W, gate_b);
    pack_x_kernel<<<MT * KCH, 256>>>(x);           // 1024 blocks
    pack_w_kernel<<<N_EXP * NT * KCH, 256>>>(W);   // 1024 blocks

    cudaFuncSetAttribute(moe_mma_kernel,
                         cudaFuncAttributeMaxDynamicSharedMemorySize, SMEM_TOTAL);
    moe_mma_kernel<<<MT * NT, NTHREADS, SMEM_TOTAL>>>(b, out);   // 512 CTAs
}

// round 14
// speedup vs baseline: 1.4628x; 1.0002x over previous
#include <cuda_runtime.h>
#include <cuda_fp16.h>
#include <math.h>
#include <stdint.h>

#define N_TOKENS 8192
#define D_IN     1024
#define D_OUT    1024
#define N_EXP    8

#define BM 128
#define BN 128
#define BK 64
#define KCH (D_IN / BK)          // 16
#define MT  (N_TOKENS / BM)      // 64
#define NT  (D_OUT / BN)         // 8
#define NTHREADS 128
#define TSTEPS (KCH * 4 * N_EXP) // 512 (kc, ks2, e) flat steps

#define A_TILE_BYTES 16384       // 128 x 64 fp16, fragment-packed
#define SMEM_A   0               // 3 x 16384 = 49152
#define SMEM_GS  49152           // gate float 128x8        (4096)
#define SMEM_GH  53248           // gate half2-broadcast    (4096)
#define SMEM_BS  57344           // bias 8x128 f32          (4096)
#define SMEM_TOTAL 61440

// ---------------------------------------------------------------------------
__device__ float  g_gate[N_TOKENS * N_EXP];
__device__ __half x_pack[(size_t)MT * KCH * 8192];           // 16 MB
__device__ __half w_pack[(size_t)N_EXP * NT * KCH * 8192];   // 16 MB

// ---------------------------------------------------------------------------
__device__ __forceinline__ uint32_t smem_u32(const void* p) {
    uint32_t a;
    asm("{ .reg .u64 t; cvta.to.shared.u64 t, %1; cvt.u32.u64 %0, t; }" : "=r"(a) : "l"(p));
    return a;
}
__device__ __forceinline__ void cp16(uint32_t d, const void* s) {
    asm volatile("cp.async.cg.shared.global [%0], [%1], 16;" :: "r"(d), "l"(s));
}
__device__ __forceinline__ void cp_commit() {
    asm volatile("cp.async.commit_group;" ::: "memory");
}
__device__ __forceinline__ void cp_wait1() {
    asm volatile("cp.async.wait_group 1;" ::: "memory");
}
__device__ __forceinline__ void mma_f16(float* d, const uint32_t* a,
                                        const uint32_t* b, const float* c) {
    asm volatile(
        "mma.sync.aligned.m16n8k16.row.col.f32.f16.f16.f32 "
        "{%0,%1,%2,%3}, {%4,%5,%6,%7}, {%8,%9}, {%10,%11,%12,%13};\n"
        : "=f"(d[0]), "=f"(d[1]), "=f"(d[2]), "=f"(d[3])
        : "r"(a[0]), "r"(a[1]), "r"(a[2]), "r"(a[3]),
          "r"(b[0]), "r"(b[1]),
          "f"(c[0]), "f"(c[1]), "f"(c[2]), "f"(c[3]));
}
__device__ __forceinline__ uint32_t h2u(float lo, float hi) {
    __half2 h = __halves2half2(__float2half_rn(lo), __float2half_rn(hi));
    return *reinterpret_cast<uint32_t*>(&h);
}
__device__ __forceinline__ uint32_t hmul2u(uint32_t a, uint32_t g) {
    __half2 r = __hmul2(*reinterpret_cast<__half2*>(&a), *reinterpret_cast<__half2*>(&g));
    return *reinterpret_cast<uint32_t*>(&r);
}

// ---------------------------------------------------------------------------
// Gate: g = softmax(x @ gate_W + gate_b), one warp per token
// ---------------------------------------------------------------------------
__global__ void gate_kernel(const float* __restrict__ x,
                            const float* __restrict__ gate_W,
                            const float* __restrict__ gate_b) {
    int warp = threadIdx.x >> 5, lane = threadIdx.x & 31;
    int token = blockIdx.x * 8 + warp;
    if (token >= N_TOKENS) return;
    const float* xr = x + (size_t)token * D_IN;
    float acc[N_EXP];
#pragma unroll
    for (int e = 0; e < N_EXP; e++) acc[e] = 0.f;
    for (int i = lane; i < D_IN; i += 32) {
        float xv = xr[i];
        const float4* gw = reinterpret_cast<const float4*>(gate_W + (size_t)i * N_EXP);
        float4 w0 = gw[0], w1 = gw[1];
        acc[0] += xv * w0.x; acc[1] += xv * w0.y; acc[2] += xv * w0.z; acc[3] += xv * w0.w;
        acc[4] += xv * w1.x; acc[5] += xv * w1.y; acc[6] += xv * w1.z; acc[7] += xv * w1.w;
    }
#pragma unroll
    for (int e = 0; e < N_EXP; e++)
#pragma unroll
        for (int o = 16; o > 0; o >>= 1)
            acc[e] += __shfl_xor_sync(0xffffffffu, acc[e], o);
    if (lane == 0) {
        float m = -1e30f;
#pragma unroll
        for (int e = 0; e < N_EXP; e++) { acc[e] += gate_b[e]; m = fmaxf(m, acc[e]); }
        float s = 0.f;
#pragma unroll
        for (int e = 0; e < N_EXP; e++) { acc[e] = expf(acc[e] - m); s += acc[e]; }
        float inv = 1.f / s;
#pragma unroll
        for (int e = 0; e < N_EXP; e++) g_gate[token * N_EXP + e] = acc[e] * inv;
    }
}

// ---------------------------------------------------------------------------
// pack_x: x_pack[mt][kc] = 128x64 tile of x, fp16, m16n8k16 A-fragment layout.
// ---------------------------------------------------------------------------
__global__ void pack_x_kernel(const float* __restrict__ x) {
    __shared__ float xs[128 * 68];
    const int blk = blockIdx.x;                  // mt*16 + kc
    const int kc = blk & 15, mt = blk >> 4;
    const int tid = threadIdx.x;

    const float* src = x + (size_t)(mt * BM) * D_IN + kc * BK;
    for (int idx = tid; idx < 2048; idx += 256) {
        int row = idx >> 4, c4 = idx & 15;
        float4 v = *reinterpret_cast<const float4*>(src + (size_t)row * D_IN + c4 * 4);
        *reinterpret_cast<float4*>(xs + row * 68 + c4 * 4) = v;
    }
    __syncthreads();

    __half* dst = x_pack + (size_t)blk * 8192;
#pragma unroll
    for (int q = 0; q < 4; q++) {
        int ent = tid + q * 256;
        int lane = ent & 31, m16 = (ent >> 5) & 7, ks2 = ent >> 8;
        int gid = lane >> 2, tig = lane & 3;
        int r0 = m16 * 16 + gid, r1 = r0 + 8, c0 = ks2 * 16 + 2 * tig;
        const float* x0 = xs + r0 * 68;
        const float* x1 = xs + r1 * 68;
        uint4 w;
        w.x = h2u(x0[c0],     x0[c0 + 1]);
        w.y = h2u(x1[c0],     x1[c0 + 1]);
        w.z = h2u(x0[c0 + 8], x0[c0 + 9]);
        w.w = h2u(x1[c0 + 8], x1[c0 + 9]);
        *reinterpret_cast<uint4*>(dst + ent * 8) = w;
    }
}

// ---------------------------------------------------------------------------
// pack_w: w_pack[e][nt][kc] = 64(k)x128(n) tile of W^T, fp16, B-fragment layout.
// ---------------------------------------------------------------------------
__global__ void pack_w_kernel(const float* __restrict__ W) {
    __shared__ float ws[64 * 132];
    const int blk = blockIdx.x;                  // (e*NT+nt)*16 + kc
    const int kc = blk & 15, nt = (blk >> 4) & 7, e = blk >> 7;
    const int tid = threadIdx.x;

    const float* src = W + ((size_t)e * D_IN + kc * BK) * D_OUT + nt * 128;
    for (int idx = tid; idx < 2048; idx += 256) {
        int il = idx >> 5, o4 = idx & 31;
        float4 v = *reinterpret_cast<const float4*>(src + (size_t)il * D_OUT + o4 * 4);
        *reinterpret_cast<float4*>(ws + il * 132 + o4 * 4) = v;
    }
    __syncthreads();

    __half* dst = w_pack + (size_t)blk * 8192;
#pragma unroll
    for (int q = 0; q < 4; q++) {
        int ent = tid + q * 256;
        int lane = ent & 31, jp = (ent >> 5) & 7, ks2 = ent >> 8;
        int gid = lane >> 2, tig = lane & 3;
        int kr = ks2 * 16 + 2 * tig;
        int cA = jp * 16 + gid, cB = cA + 8;
        uint4 w;
        w.x = h2u(ws[kr * 132 + cA],       ws[(kr + 1) * 132 + cA]);
        w.y = h2u(ws[(kr + 8) * 132 + cA], ws[(kr + 9) * 132 + cA]);
        w.z = h2u(ws[kr * 132 + cB],       ws[(kr + 1) * 132 + cB]);
        w.w = h2u(ws[(kr + 8) * 132 + cB], ws[(kr + 9) * 132 + cB]);
        *reinterpret_cast<uint4*>(dst + ent * 8) = w;
    }
}

// ---------------------------------------------------------------------------
// Hot GEMM: 128x128 CTA tile, 4 warps 2(m) x 2(n), warp tile 64x64, occ 2.
// A: 3-stage cp.async smem, staged once per kc, af held across 8 experts.
// B: direct LDG.128 from fragment-packed global (L2/L1), rolling prefetch.
// Barriers only at kc boundaries (16 total). Gate via HMUL2 on A fragments.
// ---------------------------------------------------------------------------
__global__ void __launch_bounds__(NTHREADS, 2)
moe_mma_kernel(const float* __restrict__ bias, float* __restrict__ out) {
    extern __shared__ char smem[];
    const int tid = threadIdx.x, wid = tid >> 5, lane = tid & 31;
    const int gid = lane >> 2, tig = lane & 3;
    const int wm = wid >> 1, wn = wid & 1;
    // co-resident CTAs share nt (B operand) -> B LDGs hit L1/L2
    const int nt = blockIdx.x >> 6, mt = blockIdx.x & 63;
    const int m0 = mt * BM, n0 = nt * BN;
    const uint32_t sb = smem_u32(smem);

    float*    g_s  = reinterpret_cast<float*>(smem + SMEM_GS);
    uint32_t* gh_s = reinterpret_cast<uint32_t*>(smem + SMEM_GH);
    float*    b_s  = reinterpret_cast<float*>(smem + SMEM_BS);
    for (int i = tid; i < BM * N_EXP; i += NTHREADS) {
        float g = g_gate[m0 * N_EXP + i];
        g_s[i] = g;
        gh_s[i] = h2u(g, g);
    }
    for (int i = tid; i < N_EXP * BN; i += NTHREADS)
        b_s[i] = bias[(size_t)(i >> 7) * D_OUT + n0 + (i & 127)];

    float acc[4][8][4];
#pragma unroll
    for (int a = 0; a < 4; a++)
#pragma unroll
        for (int b = 0; b < 8; b++)
#pragma unroll
            for (int c = 0; c < 4; c++) acc[a][b][c] = 0.f;

    auto issueA = [&](int kc, int buf) {
        const char* src = (const char*)(x_pack + (size_t)(mt * KCH + kc) * 8192);
        uint32_t d = sb + SMEM_A + buf * A_TILE_BYTES + tid * 16;
#pragma unroll
        for (int r = 0; r < 8; r++) cp16(d + r * 2048, src + tid * 16 + r * 2048);
        cp_commit();
    };

    // flat step t = ((kc*4 + ks2) << 3) + e ; B fragment base for step t
    auto bload = [&](int t, uint4* dst) {
        int kcx = t >> 5, ks2x = (t >> 3) & 3, ex = t & 7;
        const uint4* p = reinterpret_cast<const uint4*>(
            (const char*)w_pack +
            ((size_t)(ex * (NT * KCH) + nt * KCH + kcx)) * (8192 * 2) +
            (size_t)(((ks2x * 8 + wn * 4) * 32) + lane) * 16);
        dst[0] = __ldg(p);
        dst[1] = __ldg(p + 32);
        dst[2] = __ldg(p + 64);
        dst[3] = __ldg(p + 96);
    };

    issueA(0, 0);
    issueA(1, 1);

    uint4 bf_n[4];
    bload(0, bf_n);

    __syncthreads();   // publish g_s/gh_s/b_s (and order before first A wait)

    for (int kc = 0; kc < KCH; ++kc) {
        cp_wait1();              // A(kc) landed (A(kc+1) may be pending)
        __syncthreads();         // all warps past kc-1's compute; A(kc) visible
        if (kc + 2 < KCH) issueA(kc + 2, (kc + 2) % 3);

        const char* ab = smem + SMEM_A + (kc % 3) * A_TILE_BYTES;
#pragma unroll
        for (int ks2 = 0; ks2 < 4; ++ks2) {
            uint4 af[4];
#pragma unroll
            for (int mtt = 0; mtt < 4; mtt++)
                af[mtt] = *reinterpret_cast<const uint4*>(
                    ab + (size_t)((ks2 * 8 + wm * 4 + mtt) * 32 + lane) * 16);

#pragma unroll 2
            for (int e = 0; e < N_EXP; ++e) {
                const int t = ((kc * 4 + ks2) << 3) + e;
                uint4 bf[4];
#pragma unroll
                for (int j = 0; j < 4; j++) bf[j] = bf_n[j];
                if (t + 1 < TSTEPS) bload(t + 1, bf_n);   // prefetch next step

                uint32_t ga, gb;
#pragma unroll
                for (int mtt = 0; mtt < 4; mtt++) {
                    int r0 = wm * 64 + mtt * 16 + gid;
                    ga = gh_s[r0 * N_EXP + e];
                    gb = gh_s[(r0 + 8) * N_EXP + e];
                    uint4 afg;
                    afg.x = hmul2u(af[mtt].x, ga);
                    afg.y = hmul2u(af[mtt].y, gb);
                    afg.z = hmul2u(af[mtt].z, ga);
                    afg.w = hmul2u(af[mtt].w, gb);
                    const uint32_t* a = reinterpret_cast<const uint32_t*>(&afg);
#pragma unroll
                    for (int ntt = 0; ntt < 8; ntt++) {
                        const uint32_t* bp =
                            reinterpret_cast<const uint32_t*>(&bf[ntt >> 1]) + (ntt & 1) * 2;
                        mma_f16(acc[mtt][ntt], a, bp, acc[mtt][ntt]);
                    }
                }
            }
        }
    }

    // ---- epilogue: gated bias + store ----
#pragma unroll
    for (int mtt = 0; mtt < 4; mtt++) {
        const int rb = wm * 64 + mtt * 16 + gid;
#pragma unroll
        for (int half = 0; half < 2; half++) {
            const int r = rb + half * 8;
            const float* gr = g_s + r * N_EXP;
            float* orow = out + (size_t)(m0 + r) * D_OUT + n0;
#pragma unroll
            for (int ntt = 0; ntt < 8; ntt++) {
                const int c = wn * 64 + ntt * 8 + 2 * tig;
                float b0 = 0.f, b1 = 0.f;
#pragma unroll
                for (int e = 0; e < N_EXP; e++) {
                    float gv = gr[e];
                    b0 += gv * b_s[e * BN + c];
                    b1 += gv * b_s[e * BN + c + 1];
                }
                float2 v;
                v.x = acc[mtt][ntt][half * 2 + 0] + b0;
                v.y = acc[mtt][ntt][half * 2 + 1] + b1;
                *reinterpret_cast<float2*>(orow + c) = v;
            }
        }
    }
}

// ---------------------------------------------------------------------------
extern "C" void kernel_launch(void* const* d_in, const int* in_sizes, int n_in,
                              void* d_out, int out_size) {
    const float* x      = (const float*)d_in[0];
    const float* W      = (const float*)d_in[1];
    const float* b      = (const float*)d_in[2];
    const float* gate_W = (const float*)d_in[3];
    const float* gate_b = (const float*)d_in[4];
    float* out = (float*)d_out;

    gate_kernel<<<N_TOKENS / 8, 256>>>(x, gate_W, gate_b);
    pack_x_kernel<<<MT * KCH, 256>>>(x);           // 1024 blocks
    pack_w_kernel<<<N_EXP * NT * KCH, 256>>>(W);   // 1024 blocks

    cudaFuncSetAttribute(moe_mma_kernel,
                         cudaFuncAttributeMaxDynamicSharedMemorySize, SMEM_TOTAL);
    moe_mma_kernel<<<MT * NT, NTHREADS, SMEM_TOTAL>>>(b, out);   // 512 CTAs
}